// round 1
// baseline (speedup 1.0000x reference)
#include <cuda_runtime.h>
#include <math.h>

#define Bn 64
#define Tn 188
#define In 512
#define Hn 1024
#define G4 (4*Hn)

// Persistent scratch (allocation-free rule: __device__ globals)
__device__ float g_prex[(size_t)Tn * Bn * G4];   // [t][b][4H]  (~197 MB)
__device__ float g_h[2][Bn * Hn];                // ping-pong hidden state
__device__ float g_c[2][Bn * Hn];                // ping-pong cell state

__device__ __forceinline__ float sigf(float x) { return 1.f / (1.f + __expf(-x)); }

// ---------------------------------------------------------------------------
// Init: copy h0/c0 into state buffer 0
// ---------------------------------------------------------------------------
__global__ void init_state(const float* __restrict__ h0, const float* __restrict__ c0) {
    int i = blockIdx.x * blockDim.x + threadIdx.x;
    if (i < Bn * Hn) {
        g_h[0][i] = h0[i];
        g_c[0][i] = c0[i];
    }
}

// ---------------------------------------------------------------------------
// Kernel A: pre_x[t][b][g] = sum_k x[b][t][k] * Wih[g][k] + bias[g]
// Tiled SGEMM: 64x64 tile, KT=32, 256 threads, 4x4 micro-tile per thread.
// Tile rows == batch (Bn==64), blockIdx.y == t.
// ---------------------------------------------------------------------------
__global__ void gemm_prex(const float* __restrict__ x,
                          const float* __restrict__ wih,
                          const float* __restrict__ bias) {
    __shared__ float As[32][68];   // [k][b]
    __shared__ float Bs[32][68];   // [k][n]
    const int t   = blockIdx.y;
    const int n0  = blockIdx.x * 64;
    const int tid = threadIdx.x;
    const int ty  = tid >> 4;      // 0..15 -> rows (b) ty*4..
    const int tx  = tid & 15;      // 0..15 -> cols (n) tx*4..

    float acc[4][4];
#pragma unroll
    for (int i = 0; i < 4; i++)
#pragma unroll
        for (int j = 0; j < 4; j++) acc[i][j] = 0.f;

    for (int k0 = 0; k0 < In; k0 += 32) {
#pragma unroll
        for (int q = 0; q < 2; q++) {
            int v   = tid + q * 256;
            int row = v >> 3;          // 0..63
            int kq  = (v & 7) * 4;     // 0..28
            float4 a = *(const float4*)&x[((size_t)row * Tn + t) * In + k0 + kq];
            As[kq + 0][row] = a.x; As[kq + 1][row] = a.y;
            As[kq + 2][row] = a.z; As[kq + 3][row] = a.w;
            float4 b = *(const float4*)&wih[(size_t)(n0 + row) * In + k0 + kq];
            Bs[kq + 0][row] = b.x; Bs[kq + 1][row] = b.y;
            Bs[kq + 2][row] = b.z; Bs[kq + 3][row] = b.w;
        }
        __syncthreads();
#pragma unroll
        for (int k = 0; k < 32; k++) {
            float4 a = *(const float4*)&As[k][ty * 4];
            float4 b = *(const float4*)&Bs[k][tx * 4];
            acc[0][0] += a.x * b.x; acc[0][1] += a.x * b.y; acc[0][2] += a.x * b.z; acc[0][3] += a.x * b.w;
            acc[1][0] += a.y * b.x; acc[1][1] += a.y * b.y; acc[1][2] += a.y * b.z; acc[1][3] += a.y * b.w;
            acc[2][0] += a.z * b.x; acc[2][1] += a.z * b.y; acc[2][2] += a.z * b.z; acc[2][3] += a.z * b.w;
            acc[3][0] += a.w * b.x; acc[3][1] += a.w * b.y; acc[3][2] += a.w * b.z; acc[3][3] += a.w * b.w;
        }
        __syncthreads();
    }

    float4 bsv = *(const float4*)&bias[n0 + tx * 4];
#pragma unroll
    for (int i = 0; i < 4; i++) {
        int b = ty * 4 + i;
        float4 o;
        o.x = acc[i][0] + bsv.x; o.y = acc[i][1] + bsv.y;
        o.z = acc[i][2] + bsv.z; o.w = acc[i][3] + bsv.w;
        *(float4*)&g_prex[((size_t)t * Bn + b) * G4 + n0 + tx * 4] = o;
    }
}

// ---------------------------------------------------------------------------
// Kernel B: one recurrent timestep.
// 128 blocks, each owns 8 hidden units (j0..j0+7) x all 64 batches.
// Rows (48): [0..7]=Whh_i, [8..15]=Whh_f, [16..23]=Whh_g, [24..31]=Whh_o,
//            [32..39]=Wrec_i, [40..47]=Wrec_f.
// Thread (rg 0..15, bgrp 0..15) accumulates rows {rg, rg+16, rg+32} x 4 batches:
// rows rg, rg+16 always use h; row rg+32 always uses c (compile-time uniform).
// ---------------------------------------------------------------------------
__global__ void __launch_bounds__(256)
step_kernel(const float* __restrict__ whh,
            const float* __restrict__ wrec,
            const int*   __restrict__ lengths,
            float* __restrict__ out,
            int t, int par, int writeC) {
    __shared__ float sh_h[32][68];
    __shared__ float sh_c[32][68];
    __shared__ float sh_w[48][36];
    __shared__ float gbuf[48][68];

    const float* __restrict__ hprev = g_h[par];
    const float* __restrict__ cprev = g_c[par];
    float* __restrict__ hnext = g_h[par ^ 1];
    float* __restrict__ cnext = g_c[par ^ 1];

    const int tid = threadIdx.x;
    const int j0  = blockIdx.x * 8;
    const int rg  = tid & 15;
    const int b0  = (tid >> 4) * 4;

    float acc0[4] = {0.f, 0.f, 0.f, 0.f};
    float acc1[4] = {0.f, 0.f, 0.f, 0.f};
    float acc2[4] = {0.f, 0.f, 0.f, 0.f};

    for (int kt = 0; kt < 32; kt++) {
        const int k0 = kt * 32;
        // load h/c tiles: [k][b], transposed from b-major global
#pragma unroll
        for (int q = 0; q < 2; q++) {
            int v  = tid + q * 256;
            int b  = v >> 3;
            int kq = (v & 7) * 4;
            float4 hv = *(const float4*)&hprev[(size_t)b * Hn + k0 + kq];
            sh_h[kq + 0][b] = hv.x; sh_h[kq + 1][b] = hv.y;
            sh_h[kq + 2][b] = hv.z; sh_h[kq + 3][b] = hv.w;
            float4 cv = *(const float4*)&cprev[(size_t)b * Hn + k0 + kq];
            sh_c[kq + 0][b] = cv.x; sh_c[kq + 1][b] = cv.y;
            sh_c[kq + 2][b] = cv.z; sh_c[kq + 3][b] = cv.w;
        }
        // load weight tile: 48 rows x 32 k = 384 float4
#pragma unroll
        for (int q = 0; q < 2; q++) {
            int v = tid + q * 256;
            if (v < 384) {
                int r   = v >> 3;
                int kq  = (v & 7) * 4;
                int j   = r & 7;
                int grp = r >> 3;   // 0..5
                const float* wp = (grp < 4)
                    ? (whh  + (size_t)(grp * Hn + j0 + j) * Hn)
                    : (wrec + (size_t)((grp - 4) * Hn + j0 + j) * Hn);
                float4 w = *(const float4*)&wp[k0 + kq];
                sh_w[r][kq + 0] = w.x; sh_w[r][kq + 1] = w.y;
                sh_w[r][kq + 2] = w.z; sh_w[r][kq + 3] = w.w;
            }
        }
        __syncthreads();

#pragma unroll
        for (int kk = 0; kk < 32; kk += 4) {
            float4 w0 = *(const float4*)&sh_w[rg][kk];
            float4 w1 = *(const float4*)&sh_w[rg + 16][kk];
            float4 w2 = *(const float4*)&sh_w[rg + 32][kk];
#define STEP_U(U, W0, W1, W2)                                                  \
            {                                                                  \
                float4 hv = *(const float4*)&sh_h[kk + U][b0];                 \
                float4 cv = *(const float4*)&sh_c[kk + U][b0];                 \
                acc0[0] += W0 * hv.x; acc0[1] += W0 * hv.y;                    \
                acc0[2] += W0 * hv.z; acc0[3] += W0 * hv.w;                    \
                acc1[0] += W1 * hv.x; acc1[1] += W1 * hv.y;                    \
                acc1[2] += W1 * hv.z; acc1[3] += W1 * hv.w;                    \
                acc2[0] += W2 * cv.x; acc2[1] += W2 * cv.y;                    \
                acc2[2] += W2 * cv.z; acc2[3] += W2 * cv.w;                    \
            }
            STEP_U(0, w0.x, w1.x, w2.x)
            STEP_U(1, w0.y, w1.y, w2.y)
            STEP_U(2, w0.z, w1.z, w2.z)
            STEP_U(3, w0.w, w1.w, w2.w)
#undef STEP_U
        }
        __syncthreads();
    }

    // stage gate partial sums
    *(float4*)&gbuf[rg][b0]      = make_float4(acc0[0], acc0[1], acc0[2], acc0[3]);
    *(float4*)&gbuf[rg + 16][b0] = make_float4(acc1[0], acc1[1], acc1[2], acc1[3]);
    *(float4*)&gbuf[rg + 32][b0] = make_float4(acc2[0], acc2[1], acc2[2], acc2[3]);
    __syncthreads();

    // elementwise LSTM cell: 512 (j,b) pairs, 2 per thread
    const size_t BTH = (size_t)Bn * Tn * Hn;
#pragma unroll
    for (int q = 0; q < 2; q++) {
        int p  = tid + q * 256;
        int j  = p & 7;
        int b  = p >> 3;
        int jj = j0 + j;
        float ii = gbuf[j][b];
        float ff = gbuf[8 + j][b];
        float gg = gbuf[16 + j][b];
        float oo = gbuf[24 + j][b];
        float ri = gbuf[32 + j][b];
        float rf = gbuf[40 + j][b];
        size_t pb = ((size_t)t * Bn + b) * G4 + jj;
        float pi = g_prex[pb];
        float pf = g_prex[pb + Hn];
        float pg = g_prex[pb + 2 * Hn];
        float po = g_prex[pb + 3 * Hn];
        float cold = cprev[(size_t)b * Hn + jj];

        float ig = sigf(pi + ii + ri);
        float fg = sigf(pf + ff + rf);
        float gv = tanhf(pg + gg);
        float cn = fg * cold + ig * gv;
        float og = sigf(po + oo + cn);
        float hn = og * tanhf(cn);
        float m  = (t < lengths[b]) ? 1.f : 0.f;
        hn *= m;
        cn *= m;

        hnext[(size_t)b * Hn + jj] = hn;
        cnext[(size_t)b * Hn + jj] = cn;
        size_t ob = ((size_t)b * Tn + t) * Hn + jj;
        out[ob] = hn;
        if (writeC) out[BTH + ob] = cn;
    }
}

// ---------------------------------------------------------------------------
extern "C" void kernel_launch(void* const* d_in, const int* in_sizes, int n_in,
                              void* d_out, int out_size) {
    const float* x       = (const float*)d_in[0];
    const float* h0      = (const float*)d_in[1];
    const float* c0      = (const float*)d_in[2];
    const float* wih     = (const float*)d_in[3];
    const float* whh     = (const float*)d_in[4];
    const float* wrec    = (const float*)d_in[5];
    const float* bias    = (const float*)d_in[6];
    const int*   lengths = (const int*)d_in[7];
    float* out = (float*)d_out;

    int writeC = (out_size >= 2 * Bn * Tn * Hn) ? 1 : 0;

    init_state<<<(Bn * Hn + 255) / 256, 256>>>(h0, c0);
    gemm_prex<<<dim3(G4 / 64, Tn), 256>>>(x, wih, bias);
    for (int t = 0; t < Tn; t++) {
        step_kernel<<<Hn / 8, 256>>>(whh, wrec, lengths, out, t, t & 1, writeC);
    }
}

// round 3
// speedup vs baseline: 3.7322x; 3.7322x over previous
#include <cuda_runtime.h>
#include <cstdint>

#define Bn 64
#define Tn 188
#define In 512
#define Hn 1024
#define G4 (4*Hn)
#define G6 (6*Hn)

// ---------------- persistent device scratch (allocation-free rule) ----------
__device__ float g_prex[(size_t)Tn * Bn * G4];     // [t][b][4H]
__device__ float g_P[2][(size_t)Bn * G6];          // split-K partials, [b][6144]
__device__ float g_h[2][Bn * Hn];                  // ping-pong hidden (fp32)
__device__ float g_c[2][Bn * Hn];                  // ping-pong cell (fp32)
__device__ float g_ht[2][Bn * Hn];                 // tf32-rounded hidden (GEMM B)
__device__ float g_ct[2][Bn * Hn];                 // tf32-rounded cell (GEMM B)
__device__ float g_W[(size_t)G6 * Hn];             // [whh;wrec] tf32-rounded
__device__ float g_Wih[(size_t)G4 * In];           // wih tf32-rounded
__device__ float g_X[(size_t)Bn * Tn * In];        // x tf32-rounded

__device__ __forceinline__ float sigf(float x){ return 1.f / (1.f + __expf(-x)); }

__device__ __forceinline__ float tf32r(float x){
    uint32_t u; asm("cvt.rna.tf32.f32 %0, %1;" : "=r"(u) : "f"(x));
    return __uint_as_float(u);
}

#define CPA16(dst, src) \
    asm volatile("cp.async.cg.shared.global [%0], [%1], 16;" :: "r"(dst), "l"(src) : "memory")
#define CPC()  asm volatile("cp.async.commit_group;" ::: "memory")
#define CPW(n) asm volatile("cp.async.wait_group %0;" :: "n"(n) : "memory")

// ---------------- smem layout (float offsets) -------------------------------
// A tiles: [128][36], B tiles: [64][36], double buffered. 36-float k-stride
// makes all mma fragment loads bank-conflict-free.
#define OA0 0
#define OA1 4608
#define OB0 9216
#define OB1 11520
#define SMEM_BYTES (13824 * 4)

#define KC 32
#define NCH 16   // both GEMMs see K-extent 512 per CTA (step uses split-K=2)

__device__ __forceinline__ void ldtile(float* s, const float* __restrict__ g,
                                       int ldK, int k0, int tid, int rows){
    const int units = rows * 8;                 // 16B units per chunk
    for (int u = tid; u < units; u += 128){
        int r  = u >> 3;
        int kq = (u & 7) * 4;
        uint32_t dst = (uint32_t)__cvta_generic_to_shared(s + r * 36 + kq);
        CPA16(dst, g + (size_t)r * ldK + k0 + kq);
    }
}

// ---------------------------------------------------------------------------
// mma.sync tf32 GEMM: D[128,64] = A[128,512] * B[64,512]^T (K-major both).
// MODE 0 (step): grid (48,2). m tiles 0..31 -> Whh x h, 32..47 -> Wrec x c.
//                blockIdx.y = K-split. Output -> g_P[split][b][6144].
// MODE 1 (prex): grid (32,188). A = Wih, B = x rows (b,t). Output -> g_prex+bias.
// ---------------------------------------------------------------------------
template<int MODE>
__global__ void __launch_bounds__(128)
gemm_mma(const float* __restrict__ bias, int par)
{
    extern __shared__ float sm[];
    const int tid  = threadIdx.x;
    const int wid  = tid >> 5;
    const int lane = tid & 31;
    const int lr   = lane >> 2;
    const int lc   = lane & 3;
    const int m    = blockIdx.x;
    const int sp   = blockIdx.y;

    const float* A; const float* B; int ldA, ldB;
    if (MODE == 0){
        A   = g_W + (size_t)m * 128 * Hn + sp * 512;
        ldA = Hn;
        B   = ((m < 32) ? g_ht[par] : g_ct[par]) + sp * 512;
        ldB = Hn;
    } else {
        A   = g_Wih + (size_t)m * 128 * In;
        ldA = In;
        B   = g_X + (size_t)sp * 64 * In;
        ldB = In;
    }

    float acc[2][8][4];
#pragma unroll
    for (int f = 0; f < 2; f++)
#pragma unroll
        for (int j = 0; j < 8; j++)
#pragma unroll
            for (int q = 0; q < 4; q++) acc[f][j][q] = 0.f;

    ldtile(sm + OA0, A, ldA, 0, tid, 128);
    ldtile(sm + OB0, B, ldB, 0, tid, 64);
    CPC();

#pragma unroll 1
    for (int ch = 0; ch < NCH; ch++){
        if (ch + 1 < NCH){
            int bo = (ch + 1) & 1;
            ldtile(sm + (bo ? OA1 : OA0), A, ldA, (ch + 1) * KC, tid, 128);
            ldtile(sm + (bo ? OB1 : OB0), B, ldB, (ch + 1) * KC, tid, 64);
            CPC();
            CPW(1);
        } else {
            CPW(0);
        }
        __syncthreads();

        const uint32_t* As = (const uint32_t*)(sm + ((ch & 1) ? OA1 : OA0));
        const uint32_t* Bs = (const uint32_t*)(sm + ((ch & 1) ? OB1 : OB0));

#pragma unroll
        for (int kk = 0; kk < 4; kk++){
            const int kb = kk * 8 + lc;
            uint32_t a[2][4], b[8][2];
#pragma unroll
            for (int fm = 0; fm < 2; fm++){
                int base = (wid * 32 + fm * 16 + lr) * 36 + kb;
                a[fm][0] = As[base];
                a[fm][1] = As[base + 8 * 36];
                a[fm][2] = As[base + 4];
                a[fm][3] = As[base + 8 * 36 + 4];
            }
#pragma unroll
            for (int j = 0; j < 8; j++){
                int bb = (j * 8 + lr) * 36 + kb;
                b[j][0] = Bs[bb];
                b[j][1] = Bs[bb + 4];
            }
#pragma unroll
            for (int fm = 0; fm < 2; fm++)
#pragma unroll
                for (int j = 0; j < 8; j++)
                    asm volatile(
                        "mma.sync.aligned.m16n8k8.row.col.f32.tf32.tf32.f32 "
                        "{%0,%1,%2,%3}, {%4,%5,%6,%7}, {%8,%9}, {%0,%1,%2,%3};"
                        : "+f"(acc[fm][j][0]), "+f"(acc[fm][j][1]),
                          "+f"(acc[fm][j][2]), "+f"(acc[fm][j][3])
                        : "r"(a[fm][0]), "r"(a[fm][1]), "r"(a[fm][2]), "r"(a[fm][3]),
                          "r"(b[j][0]), "r"(b[j][1]));
        }
        __syncthreads();
    }

    // ---------------- epilogue ----------------
    const int rowbase = m * 128 + wid * 32;
    if (MODE == 0){
        float* __restrict__ P = g_P[sp];
#pragma unroll
        for (int fm = 0; fm < 2; fm++)
#pragma unroll
            for (int j = 0; j < 8; j++)
#pragma unroll
                for (int q = 0; q < 4; q++){
                    int row = rowbase + fm * 16 + lr + (q >> 1) * 8;
                    int col = j * 8 + lc * 2 + (q & 1);
                    P[(size_t)col * G6 + row] = acc[fm][j][q];
                }
    } else {
        float bs[2][2];
#pragma unroll
        for (int fm = 0; fm < 2; fm++){
            bs[fm][0] = bias[rowbase + fm * 16 + lr];
            bs[fm][1] = bias[rowbase + fm * 16 + lr + 8];
        }
        const int n0 = sp * 64;
#pragma unroll
        for (int fm = 0; fm < 2; fm++)
#pragma unroll
            for (int j = 0; j < 8; j++)
#pragma unroll
                for (int q = 0; q < 4; q++){
                    int row = rowbase + fm * 16 + lr + (q >> 1) * 8;
                    int n   = n0 + j * 8 + lc * 2 + (q & 1);
                    int bq  = n / Tn;
                    int tq  = n - bq * Tn;
                    g_prex[((size_t)tq * Bn + bq) * G4 + row] =
                        acc[fm][j][q] + bs[fm][q >> 1];
                }
    }
}

// ---------------------------------------------------------------------------
__global__ void cvt_all(const float* __restrict__ whh, const float* __restrict__ wrec,
                        const float* __restrict__ wih, const float* __restrict__ x)
{
    const size_t n0 = (size_t)4096 * 1024;
    const size_t n1 = (size_t)2048 * 1024;
    const size_t n2 = (size_t)4096 * 512;
    const size_t n3 = (size_t)Bn * Tn * In;
    const size_t NT = n0 + n1 + n2 + n3;
    for (size_t i = (size_t)blockIdx.x * blockDim.x + threadIdx.x; i < NT;
         i += (size_t)gridDim.x * blockDim.x){
        if (i < n0)                g_W[i]                 = tf32r(whh[i]);
        else if (i < n0 + n1)      g_W[i]                 = tf32r(wrec[i - n0]);
        else if (i < n0 + n1 + n2) g_Wih[i - n0 - n1]     = tf32r(wih[i - n0 - n1]);
        else                       g_X[i - n0 - n1 - n2]  = tf32r(x[i - n0 - n1 - n2]);
    }
}

__global__ void init_state(const float* __restrict__ h0, const float* __restrict__ c0){
    int i = blockIdx.x * blockDim.x + threadIdx.x;
    if (i < Bn * Hn){
        float h = h0[i], c = c0[i];
        g_h[0][i] = h;  g_c[0][i] = c;
        g_ht[0][i] = tf32r(h);  g_ct[0][i] = tf32r(c);
    }
}

__global__ void __launch_bounds__(256)
cell_kernel(const int* __restrict__ lengths, float* __restrict__ out,
            int t, int par, int writeC)
{
    int idx = blockIdx.x * 256 + threadIdx.x;    // 0..65535
    int j = idx & (Hn - 1);
    int b = idx >> 10;

    const float* __restrict__ P0 = g_P[0] + (size_t)b * G6;
    const float* __restrict__ P1 = g_P[1] + (size_t)b * G6;
    size_t pxb = ((size_t)t * Bn + b) * G4 + j;

    float pi = g_prex[pxb]          + P0[j]          + P1[j]
             + P0[4 * Hn + j] + P1[4 * Hn + j];
    float pf = g_prex[pxb + Hn]     + P0[Hn + j]     + P1[Hn + j]
             + P0[5 * Hn + j] + P1[5 * Hn + j];
    float pg = g_prex[pxb + 2 * Hn] + P0[2 * Hn + j] + P1[2 * Hn + j];
    float po = g_prex[pxb + 3 * Hn] + P0[3 * Hn + j] + P1[3 * Hn + j];
    float cold = g_c[par][b * Hn + j];

    float ig = sigf(pi);
    float fg = sigf(pf);
    float gv = tanhf(pg);
    float cn = fg * cold + ig * gv;
    float og = sigf(po + cn);
    float hn = og * tanhf(cn);
    float mval = (t < lengths[b]) ? 1.f : 0.f;
    hn *= mval; cn *= mval;

    int np = par ^ 1;
    g_h[np][b * Hn + j]  = hn;
    g_c[np][b * Hn + j]  = cn;
    g_ht[np][b * Hn + j] = tf32r(hn);
    g_ct[np][b * Hn + j] = tf32r(cn);

    size_t ob = ((size_t)b * Tn + t) * Hn + j;
    out[ob] = hn;
    if (writeC) out[(size_t)Bn * Tn * Hn + ob] = cn;
}

// ---------------------------------------------------------------------------
extern "C" void kernel_launch(void* const* d_in, const int* in_sizes, int n_in,
                              void* d_out, int out_size)
{
    const float* x    = (const float*)d_in[0];
    const float* h0   = (const float*)d_in[1];
    const float* c0   = (const float*)d_in[2];
    const float* wih  = (const float*)d_in[3];
    const float* whh  = (const float*)d_in[4];
    const float* wrec = (const float*)d_in[5];
    const float* bias = (const float*)d_in[6];
    const int* lengths = (const int*)d_in[7];
    float* out = (float*)d_out;
    int writeC = (out_size >= 2 * Bn * Tn * Hn) ? 1 : 0;

    cudaFuncSetAttribute(gemm_mma<0>, cudaFuncAttributeMaxDynamicSharedMemorySize, SMEM_BYTES);
    cudaFuncSetAttribute(gemm_mma<1>, cudaFuncAttributeMaxDynamicSharedMemorySize, SMEM_BYTES);

    cvt_all<<<4096, 256>>>(whh, wrec, wih, x);
    init_state<<<256, 256>>>(h0, c0);
    gemm_mma<1><<<dim3(32, 188), 128, SMEM_BYTES>>>(bias, 0);
    for (int t = 0; t < Tn; t++){
        gemm_mma<0><<<dim3(48, 2), 128, SMEM_BYTES>>>(nullptr, t & 1);
        cell_kernel<<<256, 256>>>(lengths, out, t, t & 1, writeC);
    }
}